// round 12
// baseline (speedup 1.0000x reference)
#include <cuda_runtime.h>

// 2-layer bidirectional GRU encoder, B=256, T=256, D=64, H=256.
// R12: gi (input transform) hoisted out of the recurrence into a 3xTF32
// tensor-core GEMM over all timesteps (no sequential dependency), leaving a
// gh-only recurrence (R11 structure: 2-CTA cluster j-split, k-split lanes,
// merging-butterfly reduce, DSMEM h exchange).
// Pipeline: gemm(gi0) -> rec0 -> gemm(gi1) -> rec1.

namespace {
constexpr int Bv  = 256;
constexpr int Tv  = 256;
constexpr int Dv  = 64;
constexpr int Hv  = 256;
constexpr int Rv  = 8;      // batch rows per cluster (== ko lanes)
constexpr int NTH = 512;    // rec: 16 warps
constexpr int JH  = Hv / 2; // j-range per rec CTA (128)
constexpr int NJJ = 2;
constexpr int PAD = 4;
constexpr int NG  = 1536;   // gi row width = 2 dirs * 3H
}

typedef unsigned long long ull;

// Scratch: layer-0 output sequence (128 MB) + gi for current layer (402 MB).
__device__ __align__(16) float g_h1[(size_t)Tv * Bv * 2 * Hv];
__device__ __align__(16) float g_gi[(size_t)Tv * Bv * NG];

__device__ __forceinline__ void ffma2(ull &acc, ull a, ull b) {
    asm("fma.rn.f32x2 %0, %1, %2, %0;" : "+l"(acc) : "l"(a), "l"(b));
}
__device__ __forceinline__ float hsum2(ull v) {
    return __uint_as_float((unsigned)(v & 0xffffffffull)) +
           __uint_as_float((unsigned)(v >> 32));
}
__device__ __forceinline__ float sigm(float x) {
    return 1.0f / (1.0f + __expf(-x));
}
__device__ __forceinline__ float tanh_fast(float x) {
    float ax = fabsf(x);
    float e  = __expf(-2.0f * ax);
    float t  = (1.0f - e) / (1.0f + e);
    return copysignf(t, x);
}
__device__ __forceinline__ float tf32r(float x) {
    float r; asm("cvt.rna.tf32.f32 %0, %1;" : "=f"(r) : "f"(x)); return r;
}
__device__ __forceinline__ unsigned ctarank() {
    unsigned r; asm("mov.u32 %0, %%cluster_ctarank;" : "=r"(r)); return r;
}
__device__ __forceinline__ unsigned mapa_peer(unsigned local_addr, unsigned rank) {
    unsigned r;
    asm("mapa.shared::cluster.u32 %0, %1, %2;" : "=r"(r) : "r"(local_addr), "r"(rank));
    return r;
}
__device__ __forceinline__ void st_cluster_f32(unsigned addr, float v) {
    asm volatile("st.shared::cluster.f32 [%0], %1;" :: "r"(addr), "f"(v) : "memory");
}
#define CLUSTER_SYNC_() do {                                          \
    asm volatile("barrier.cluster.arrive.aligned;" ::: "memory");     \
    asm volatile("barrier.cluster.wait.aligned;"   ::: "memory");     \
} while (0)

__device__ __forceinline__ void mma_tf32(float c[4],
        unsigned a0, unsigned a1, unsigned a2, unsigned a3,
        unsigned b0, unsigned b1) {
    asm volatile(
        "mma.sync.aligned.m16n8k8.row.col.f32.tf32.tf32.f32 "
        "{%0,%1,%2,%3}, {%4,%5,%6,%7}, {%8,%9}, {%0,%1,%2,%3};"
        : "+f"(c[0]), "+f"(c[1]), "+f"(c[2]), "+f"(c[3])
        : "r"(a0), "r"(a1), "r"(a2), "r"(a3), "r"(b0), "r"(b1));
}

// Reduce 8 register arrays over the 8 ko-lanes; lane ko returns sum of v[ko].
__device__ __forceinline__ float tree8(const float v[8], int ko) {
    float u[4];
    #pragma unroll
    for (int i = 0; i < 4; i++) {
        const float a = v[2 * i], b = v[2 * i + 1];
        const float send = (ko & 1) ? a : b;
        const float recv = __shfl_xor_sync(0xffffffffu, send, 1);
        u[i] = ((ko & 1) ? b : a) + recv;
    }
    float w2[2];
    #pragma unroll
    for (int i = 0; i < 2; i++) {
        const float a = u[2 * i], b = u[2 * i + 1];
        const float send = (ko & 2) ? a : b;
        const float recv = __shfl_xor_sync(0xffffffffu, send, 2);
        w2[i] = ((ko & 2) ? b : a) + recv;
    }
    const float a = w2[0], b = w2[1];
    const float send = (ko & 4) ? a : b;
    const float recv = __shfl_xor_sync(0xffffffffu, send, 4);
    return ((ko & 4) ? b : a) + recv;
}

// ===================== gi GEMM (3xTF32 mma.sync) =====================
// C[m, n] = sum_k A[m,k] * W[n,k];  m = t*256+b (65536), n = dir*768+g (1536).
// XA=true: A = x (B,T,D) -> row m at ((m&255)*Tv + (m>>8))*Dv.
template<int KA, bool XA>
__global__ void __launch_bounds__(256)
gi_gemm(const float* __restrict__ A, const float* __restrict__ W,
        float* __restrict__ gi)
{
    constexpr int BM = 128, BN = 64, BK = 16;
    __shared__ float As_hi[BK][BM + 2], As_lo[BK][BM + 2];
    __shared__ float Bs_hi[BK][BN + 2], Bs_lo[BK][BN + 2];

    const int tid = threadIdx.x, l = tid & 31, wid = tid >> 5;
    const int m0 = blockIdx.x * BM, n0 = blockIdx.y * BN;
    const int wm = (wid >> 1) * 32, wn = (wid & 1) * 32;

    float c[2][4][4] = {};

    for (int kc = 0; kc < KA; kc += BK) {
        // stage A tile (128 x 16): 2 float4 per thread, hi/lo split
        #pragma unroll
        for (int i = 0; i < 2; i++) {
            const int e  = tid + i * 256;   // 0..511
            const int m  = e >> 2;
            const int k4 = e & 3;
            const float* ap;
            if (XA) {
                const int mg = m0 + m;
                ap = A + ((size_t)(mg & 255) * Tv + (mg >> 8)) * Dv;
            } else {
                ap = A + (size_t)(m0 + m) * KA;
            }
            const float4 v = *reinterpret_cast<const float4*>(ap + kc + k4 * 4);
            const float f[4] = {v.x, v.y, v.z, v.w};
            #pragma unroll
            for (int q = 0; q < 4; q++) {
                const float hi = tf32r(f[q]);
                As_hi[k4 * 4 + q][m] = hi;
                As_lo[k4 * 4 + q][m] = tf32r(f[q] - hi);
            }
        }
        // stage W tile (64 x 16): 1 float4 per thread
        {
            const int n  = tid >> 2;
            const int k4 = tid & 3;
            const float4 v = *reinterpret_cast<const float4*>(
                W + (size_t)(n0 + n) * KA + kc + k4 * 4);
            const float f[4] = {v.x, v.y, v.z, v.w};
            #pragma unroll
            for (int q = 0; q < 4; q++) {
                const float hi = tf32r(f[q]);
                Bs_hi[k4 * 4 + q][n] = hi;
                Bs_lo[k4 * 4 + q][n] = tf32r(f[q] - hi);
            }
        }
        __syncthreads();

        #pragma unroll
        for (int k8 = 0; k8 < BK / 8; k8++) {
            const int kk = k8 * 8 + (l & 3);
            unsigned ah[2][4], al[2][4], bh[4][2], bl[4][2];
            #pragma unroll
            for (int mt = 0; mt < 2; mt++) {
                const int r = wm + mt * 16 + (l >> 2);
                ah[mt][0] = __float_as_uint(As_hi[kk][r]);
                ah[mt][1] = __float_as_uint(As_hi[kk][r + 8]);
                ah[mt][2] = __float_as_uint(As_hi[kk + 4][r]);
                ah[mt][3] = __float_as_uint(As_hi[kk + 4][r + 8]);
                al[mt][0] = __float_as_uint(As_lo[kk][r]);
                al[mt][1] = __float_as_uint(As_lo[kk][r + 8]);
                al[mt][2] = __float_as_uint(As_lo[kk + 4][r]);
                al[mt][3] = __float_as_uint(As_lo[kk + 4][r + 8]);
            }
            #pragma unroll
            for (int nt = 0; nt < 4; nt++) {
                const int n = wn + nt * 8 + (l >> 2);
                bh[nt][0] = __float_as_uint(Bs_hi[kk][n]);
                bh[nt][1] = __float_as_uint(Bs_hi[kk + 4][n]);
                bl[nt][0] = __float_as_uint(Bs_lo[kk][n]);
                bl[nt][1] = __float_as_uint(Bs_lo[kk + 4][n]);
            }
            #pragma unroll
            for (int mt = 0; mt < 2; mt++)
                #pragma unroll
                for (int nt = 0; nt < 4; nt++) {
                    mma_tf32(c[mt][nt], ah[mt][0], ah[mt][1], ah[mt][2], ah[mt][3],
                             bh[nt][0], bh[nt][1]);                       // hi*hi
                    mma_tf32(c[mt][nt], ah[mt][0], ah[mt][1], ah[mt][2], ah[mt][3],
                             bl[nt][0], bl[nt][1]);                       // hi*lo
                    mma_tf32(c[mt][nt], al[mt][0], al[mt][1], al[mt][2], al[mt][3],
                             bh[nt][0], bh[nt][1]);                       // lo*hi
                }
        }
        __syncthreads();
    }

    // writeout: c0,c1 -> (row, 2n..2n+1); c2,c3 -> (row+8, same cols)
    #pragma unroll
    for (int mt = 0; mt < 2; mt++)
        #pragma unroll
        for (int nt = 0; nt < 4; nt++) {
            const int r0  = m0 + wm + mt * 16 + (l >> 2);
            const int col = n0 + wn + nt * 8 + (l & 3) * 2;
            *reinterpret_cast<float2*>(gi + (size_t)r0 * NG + col) =
                make_float2(c[mt][nt][0], c[mt][nt][1]);
            *reinterpret_cast<float2*>(gi + (size_t)(r0 + 8) * NG + col) =
                make_float2(c[mt][nt][2], c[mt][nt][3]);
        }
}

// ===================== gh-only recurrence =====================
template<bool IS_L0>
__global__ void __launch_bounds__(NTH, 1) __cluster_dims__(2, 1, 1)
gru_rec(const float* __restrict__ whh,    // (2, 3H, H)
        const float* __restrict__ bih,    // (2, 3H)
        const float* __restrict__ bhh,    // (2, 3H)
        const float* __restrict__ gi,     // (T, B, 2, 3H) = (T*B, NG)
        float* __restrict__ seq_out,      // L0: g_h1
        float* __restrict__ fin_out)      // L1: d_out (B, 2H)
{
    const int tid  = threadIdx.x;
    const int w    = tid >> 5;
    const int lane = tid & 31;
    const int ko   = lane & 7;
    const int jo   = lane >> 3;
    const unsigned c = ctarank();
    const int b0   = (blockIdx.x >> 1) * Rv;
    const int dir  = blockIdx.y;

    __shared__ __align__(16) float hs[2][Rv][Hv + PAD];     // full h, dbl-buf
    __shared__ __align__(16) float gs[Rv][3][JH + PAD];     // staged gi

    const size_t g3 = (size_t)dir * 3 * Hv;
    const int jbase = (int)c * JH + w * (JH / 16) + jo;

    const unsigned my_hs   = (unsigned)__cvta_generic_to_shared(&hs[0][0][0]);
    const unsigned peer_hs = mapa_peer(my_hs, c ^ 1u);

    float bR_[NJJ], bZ_[NJJ], bIN_[NJJ], bHN_[NJJ];
    #pragma unroll
    for (int jj = 0; jj < NJJ; jj++) {
        const int j = jbase + jj * 4;
        bR_[jj]  = bih[g3 + j]          + bhh[g3 + j];
        bZ_[jj]  = bih[g3 + Hv + j]     + bhh[g3 + Hv + j];
        bIN_[jj] = bih[g3 + 2 * Hv + j];
        bHN_[jj] = bhh[g3 + 2 * Hv + j];
    }

    for (int i = tid; i < 2 * Rv * (Hv + PAD); i += NTH)
        (&hs[0][0][0])[i] = 0.0f;
    __syncthreads();
    CLUSTER_SYNC_();

    int p = 0;
    for (int s = 0; s < Tv; s++) {
        const int tt = dir ? (Tv - 1 - s) : s;

        // ---- stage gi rows: 8 rows x 3 gates x 128 floats (float4) ----
        for (int i = tid; i < Rv * 3 * (JH / 4); i += NTH) {
            const int rr = i / 96;
            const int gg = (i % 96) / 32;
            const int cc = i % 32;
            const float4 v = *reinterpret_cast<const float4*>(
                gi + ((size_t)tt * Bv + (b0 + rr)) * NG +
                (size_t)dir * 768 + gg * Hv + (int)c * JH + cc * 4);
            *reinterpret_cast<float4*>(&gs[rr][gg][cc * 4]) = v;
        }
        __syncthreads();

        const float (*hc)[Hv + PAD] = hs[p];
        float (*hn)[Hv + PAD]       = hs[p ^ 1];
        const unsigned peer_hn =
            peer_hs + (unsigned)((p ^ 1) * Rv * (Hv + PAD)) * 4u;

        #pragma unroll 1
        for (int jj = 0; jj < NJJ; jj++) {
            const int j    = jbase + jj * 4;
            const int jloc = w * (JH / 16) + jj * 4 + jo;

            ull aR[Rv], aZ[Rv], aN[Rv];
            #pragma unroll
            for (int r = 0; r < Rv; r++) { aR[r] = 0; aZ[r] = 0; aN[r] = 0; }

            // ---- gh = h . w_hh^T (k-split over ko) ----
            {
                const float* ur_ = whh + (g3 + j) * Hv;
                const float* uz_ = whh + (g3 + Hv + j) * Hv;
                const float* un_ = whh + (g3 + 2 * Hv + j) * Hv;
                #pragma unroll 2
                for (int k = 0; k < Hv; k += 32) {
                    const int kk = k + ko * 4;
                    const ulonglong2 w_r = *reinterpret_cast<const ulonglong2*>(ur_ + kk);
                    const ulonglong2 w_z = *reinterpret_cast<const ulonglong2*>(uz_ + kk);
                    const ulonglong2 w_n = *reinterpret_cast<const ulonglong2*>(un_ + kk);
                    #pragma unroll
                    for (int r = 0; r < Rv; r++) {
                        const ulonglong2 h2 =
                            *reinterpret_cast<const ulonglong2*>(&hc[r][kk]);
                        ffma2(aR[r], w_r.x, h2.x); ffma2(aR[r], w_r.y, h2.y);
                        ffma2(aZ[r], w_z.x, h2.x); ffma2(aZ[r], w_z.y, h2.y);
                        ffma2(aN[r], w_n.x, h2.x); ffma2(aN[r], w_n.y, h2.y);
                    }
                }
            }

            float vR[Rv], vZ[Rv], vN[Rv];
            #pragma unroll
            for (int r = 0; r < Rv; r++) {
                vR[r] = hsum2(aR[r]); vZ[r] = hsum2(aZ[r]); vN[r] = hsum2(aN[r]);
            }
            const float sR = tree8(vR, ko);
            const float sZ = tree8(vZ, ko);
            const float sN = tree8(vN, ko);

            // gi from staged smem (precomputed GEMM, bias-free)
            const float giR = gs[ko][0][jloc];
            const float giZ = gs[ko][1][jloc];
            const float giN = gs[ko][2][jloc];

            // PyTorch gate convention: b_hh_n inside r*
            const float rg = sigm(sR + giR + bR_[jj]);
            const float zg = sigm(sZ + giZ + bZ_[jj]);
            const float ng = tanh_fast(giN + bIN_[jj] + rg * (sN + bHN_[jj]));
            const float hv = (1.0f - zg) * ng + zg * hc[ko][j];

            hn[ko][j] = hv;
            st_cluster_f32(peer_hn + (unsigned)(ko * (Hv + PAD) + j) * 4u, hv);
            if (IS_L0)
                seq_out[((size_t)tt * Bv + (b0 + ko)) * (2 * Hv) +
                        (size_t)dir * Hv + j] = hv;
        }
        CLUSTER_SYNC_();   // peer h visible; also orders gs reuse
        p ^= 1;
    }

    if (!IS_L0) {
        #pragma unroll
        for (int jj = 0; jj < NJJ; jj++) {
            const int j = jbase + jj * 4;
            fin_out[(size_t)(b0 + ko) * (2 * Hv) + (size_t)dir * Hv + j] =
                hs[p][ko][j];
        }
    }
}

extern "C" void kernel_launch(void* const* d_in, const int* in_sizes, int n_in,
                              void* d_out, int out_size) {
    const float* x     = (const float*)d_in[0];
    const float* w_ih0 = (const float*)d_in[1];
    const float* w_hh0 = (const float*)d_in[2];
    const float* b_ih0 = (const float*)d_in[3];
    const float* b_hh0 = (const float*)d_in[4];
    const float* w_ih1 = (const float*)d_in[5];
    const float* w_hh1 = (const float*)d_in[6];
    const float* b_ih1 = (const float*)d_in[7];
    const float* b_hh1 = (const float*)d_in[8];
    float* out = (float*)d_out;

    float *h1 = nullptr, *gi = nullptr;
    cudaGetSymbolAddress((void**)&h1, g_h1);
    cudaGetSymbolAddress((void**)&gi, g_gi);

    const dim3 ggrid((Tv * Bv) / 128, NG / 64);   // (512, 24)
    const dim3 rgrid(2 * (Bv / Rv), 2);           // 128 CTAs, cluster (2,1,1)

    gi_gemm<Dv,     true ><<<ggrid, 256>>>(x,  w_ih0, gi);
    gru_rec<true ><<<rgrid, NTH>>>(w_hh0, b_ih0, b_hh0, gi, h1, nullptr);
    gi_gemm<2 * Hv, false><<<ggrid, 256>>>(h1, w_ih1, gi);
    gru_rec<false><<<rgrid, NTH>>>(w_hh1, b_ih1, b_hh1, gi, nullptr, out);
}